// round 1
// baseline (speedup 1.0000x reference)
#include <cuda_runtime.h>
#include <cuda_bf16.h>
#include <math_constants.h>

#define NN 50000
#define EE 800000
#define DD 128
#define NEG_SLOPE 0.2f

// ---------------- device scratch (static, no allocation) ----------------
__device__ float g_h[(size_t)NN * DD];   // transformed features
__device__ float g_as[NN];
__device__ float g_ad[NN];
__device__ int   g_deg[NN];
__device__ int   g_off[NN + 1];
__device__ int   g_cur[NN];
__device__ int   g_ssrc[EE];             // edge src sorted by dst
__device__ float g_es[EE];               // edge logit (leaky-relu'd) sorted by dst

// ---------------- 1) GEMM: h = x @ W  (64x128x128 tile, fp32) ----------------
// blockDim (16,16); each thread computes a 4x8 micro-tile.
__global__ void gat_gemm(const float* __restrict__ x, const float* __restrict__ W)
{
    extern __shared__ float sm[];
    float* xs = sm;               // [64][128]
    float* ws = sm + 64 * 128;    // [128][128]

    const int tx = threadIdx.x, ty = threadIdx.y;
    const int tid = ty * 16 + tx;
    const int m0 = blockIdx.x * 64;

    // load W (full 128x128) — same linear layout as global
    #pragma unroll
    for (int t = 0; t < 16; t++) {
        int idx = tid + 256 * t;                 // float4 index, 0..4095
        ((float4*)ws)[idx] = ((const float4*)W)[idx];
    }
    // load x tile [64][128], zero-pad OOB rows
    #pragma unroll
    for (int t = 0; t < 8; t++) {
        int idx = tid + 256 * t;                 // 0..2047
        int r = idx >> 5;                        // row in tile
        int c4 = idx & 31;                       // float4 col
        int row = m0 + r;
        float4 v = make_float4(0.f, 0.f, 0.f, 0.f);
        if (row < NN) v = ((const float4*)x)[(size_t)row * 32 + c4];
        ((float4*)xs)[idx] = v;
    }
    __syncthreads();

    float acc[4][8];
    #pragma unroll
    for (int i = 0; i < 4; i++)
        #pragma unroll
        for (int j = 0; j < 8; j++) acc[i][j] = 0.f;

    #pragma unroll 8
    for (int k = 0; k < 128; k++) {
        float xv[4];
        #pragma unroll
        for (int i = 0; i < 4; i++) xv[i] = xs[(ty + 16 * i) * 128 + k];
        float4 w0 = ((float4*)(ws + k * 128))[tx * 2];
        float4 w1 = ((float4*)(ws + k * 128))[tx * 2 + 1];
        float wv[8] = {w0.x, w0.y, w0.z, w0.w, w1.x, w1.y, w1.z, w1.w};
        #pragma unroll
        for (int i = 0; i < 4; i++)
            #pragma unroll
            for (int j = 0; j < 8; j++)
                acc[i][j] = fmaf(xv[i], wv[j], acc[i][j]);
    }

    // store
    #pragma unroll
    for (int i = 0; i < 4; i++) {
        int row = m0 + ty + 16 * i;
        if (row < NN) {
            float4 s0 = make_float4(acc[i][0], acc[i][1], acc[i][2], acc[i][3]);
            float4 s1 = make_float4(acc[i][4], acc[i][5], acc[i][6], acc[i][7]);
            ((float4*)(g_h + (size_t)row * 128))[tx * 2]     = s0;
            ((float4*)(g_h + (size_t)row * 128))[tx * 2 + 1] = s1;
        }
    }
}

// ---------------- 2) per-node attention halves: a_s = h.att_src, a_d = h.att_dst ----
__global__ void gat_asd(const float* __restrict__ att_s, const float* __restrict__ att_d)
{
    int warp = (blockIdx.x * blockDim.x + threadIdx.x) >> 5;
    int lane = threadIdx.x & 31;
    if (warp >= NN) return;
    float4 hv = ((const float4*)(g_h + (size_t)warp * 128))[lane];
    float4 sv = ((const float4*)att_s)[lane];
    float4 dv = ((const float4*)att_d)[lane];
    float ps = hv.x * sv.x + hv.y * sv.y + hv.z * sv.z + hv.w * sv.w;
    float pd = hv.x * dv.x + hv.y * dv.y + hv.z * dv.z + hv.w * dv.w;
    #pragma unroll
    for (int s = 16; s; s >>= 1) {
        ps += __shfl_xor_sync(0xffffffffu, ps, s);
        pd += __shfl_xor_sync(0xffffffffu, pd, s);
    }
    if (lane == 0) { g_as[warp] = ps; g_ad[warp] = pd; }
}

// ---------------- 3) CSR build ----------------
__global__ void gat_zero_deg()
{
    int i = blockIdx.x * blockDim.x + threadIdx.x;
    if (i < NN) g_deg[i] = 0;
}

__global__ void gat_hist(const int* __restrict__ dst)
{
    int i = blockIdx.x * blockDim.x + threadIdx.x;
    if (i < EE) atomicAdd(&g_deg[dst[i]], 1);
}

// single block, 1024 threads: exclusive scan of degrees -> offsets + cursors
__global__ void gat_scan()
{
    __shared__ int s[1024];
    const int tid = threadIdx.x;
    const int C = (NN + 1023) / 1024;     // 49
    int start = tid * C;
    int end = start + C; if (end > NN) end = NN;
    if (start > NN) start = NN;

    int sum = 0;
    for (int i = start; i < end; i++) sum += g_deg[i];
    s[tid] = sum;
    for (int o = 1; o < 1024; o <<= 1) {
        __syncthreads();
        int v = (tid >= o) ? s[tid - o] : 0;
        __syncthreads();
        s[tid] += v;
    }
    __syncthreads();
    int run = s[tid] - sum;               // exclusive prefix
    for (int i = start; i < end; i++) {
        g_off[i] = run;
        g_cur[i] = run;
        run += g_deg[i];
    }
    if (tid == 1023) g_off[NN] = s[1023]; // = E
}

__global__ void gat_scatter(const int* __restrict__ src, const int* __restrict__ dst)
{
    int i = blockIdx.x * blockDim.x + threadIdx.x;
    if (i >= EE) return;
    int sv = src[i], dv = dst[i];
    int pos = atomicAdd(&g_cur[dv], 1);
    float t = g_as[sv] + g_ad[dv];
    float e = t > 0.f ? t : NEG_SLOPE * t;
    g_ssrc[pos] = sv;
    g_es[pos]   = e;
}

// ---------------- 4) per-dst softmax + aggregate + fused epilogue ----------------
// one warp per destination node
__global__ void gat_aggregate(const float* __restrict__ x,
                              const float* __restrict__ bias,
                              const float* __restrict__ gamma,
                              const float* __restrict__ beta,
                              float* __restrict__ out)
{
    int u = blockIdx.x * (blockDim.x >> 5) + (threadIdx.x >> 5);
    int lane = threadIdx.x & 31;
    if (u >= NN) return;

    int o  = g_off[u];
    int oe = g_off[u + 1];
    int deg = oe - o;

    float4 acc = make_float4(0.f, 0.f, 0.f, 0.f);

    if (deg > 0) {
        // pass 1: segment max
        float m = -CUDART_INF_F;
        for (int j = lane; j < deg; j += 32) m = fmaxf(m, g_es[o + j]);
        #pragma unroll
        for (int s = 16; s; s >>= 1) m = fmaxf(m, __shfl_xor_sync(0xffffffffu, m, s));
        // pass 2: sum exp
        float sum = 0.f;
        for (int j = lane; j < deg; j += 32) sum += __expf(g_es[o + j] - m);
        #pragma unroll
        for (int s = 16; s; s >>= 1) sum += __shfl_xor_sync(0xffffffffu, sum, s);
        float inv = 1.f / sum;
        // pass 3: weighted feature gather (all lanes iterate edges together)
        for (int j = 0; j < deg; j++) {
            float alpha = __expf(g_es[o + j] - m) * inv;   // broadcast load
            int sidx = g_ssrc[o + j];                      // broadcast load
            float4 hv = ((const float4*)(g_h + (size_t)sidx * 128))[lane];
            acc.x = fmaf(alpha, hv.x, acc.x);
            acc.y = fmaf(alpha, hv.y, acc.y);
            acc.z = fmaf(alpha, hv.z, acc.z);
            acc.w = fmaf(alpha, hv.w, acc.w);
        }
    }

    // epilogue: bias -> BN(eval) -> ReLU -> residual
    const float inv_s = rsqrtf(1.0f + 1e-5f);
    float4 bv = ((const float4*)bias)[lane];
    float4 gv = ((const float4*)gamma)[lane];
    float4 be = ((const float4*)beta)[lane];
    float4 xv = ((const float4*)(x + (size_t)u * 128))[lane];

    float4 r;
    r.x = xv.x + fmaxf(gv.x * ((acc.x + bv.x) * inv_s) + be.x, 0.f);
    r.y = xv.y + fmaxf(gv.y * ((acc.y + bv.y) * inv_s) + be.y, 0.f);
    r.z = xv.z + fmaxf(gv.z * ((acc.z + bv.z) * inv_s) + be.z, 0.f);
    r.w = xv.w + fmaxf(gv.w * ((acc.w + bv.w) * inv_s) + be.w, 0.f);

    ((float4*)(out + (size_t)u * 128))[lane] = r;
}

// ---------------- launch ----------------
extern "C" void kernel_launch(void* const* d_in, const int* in_sizes, int n_in,
                              void* d_out, int out_size)
{
    const float* x        = (const float*)d_in[0];
    const int*   edge     = (const int*)d_in[1];   // [2, E]: src row then dst row
    const float* W        = (const float*)d_in[2];
    const float* att_src  = (const float*)d_in[3];
    const float* att_dst  = (const float*)d_in[4];
    const float* bias     = (const float*)d_in[5];
    const float* gamma    = (const float*)d_in[6];
    const float* beta     = (const float*)d_in[7];
    float* out            = (float*)d_out;

    const int* src = edge;
    const int* dst = edge + EE;

    // GEMM needs 96KB dynamic smem
    static const size_t GEMM_SMEM = (64 * 128 + 128 * 128) * sizeof(float);
    cudaFuncSetAttribute(gat_gemm, cudaFuncAttributeMaxDynamicSharedMemorySize,
                         (int)GEMM_SMEM);

    dim3 gemmBlock(16, 16);
    gat_gemm<<<(NN + 63) / 64, gemmBlock, GEMM_SMEM>>>(x, W);

    gat_asd<<<(NN * 32 + 255) / 256, 256>>>(att_src, att_dst);

    gat_zero_deg<<<(NN + 255) / 256, 256>>>();
    gat_hist<<<(EE + 255) / 256, 256>>>(dst);
    gat_scan<<<1, 1024>>>();
    gat_scatter<<<(EE + 255) / 256, 256>>>(src, dst);

    gat_aggregate<<<(NN + 7) / 8, 256>>>(x, bias, gamma, beta, out);
}

// round 2
// speedup vs baseline: 1.1596x; 1.1596x over previous
#include <cuda_runtime.h>
#include <cuda_bf16.h>
#include <math_constants.h>

#define NN 50000
#define EE 800000
#define DD 128
#define NEG_SLOPE 0.2f
#define XS_STRIDE 132   // padded to break bank conflicts on broadcast loads

// ---------------- device scratch (static, no allocation) ----------------
__device__ float g_h[(size_t)NN * DD];   // transformed features
__device__ float g_as[NN];
__device__ float g_ad[NN];
__device__ int   g_deg[NN];
__device__ int   g_off[NN + 1];
__device__ int   g_cur[NN];
__device__ int   g_ssrc[EE];             // edge src sorted by dst
__device__ float g_es[EE];               // edge logit (leaky-relu'd) sorted by dst

// ---------------- 1) GEMM: h = x @ W, fused a_s/a_d epilogue ----------------
// 128x128x128 block tile, blockDim (16,16), 8x8 register microtile per thread.
// Thread (tx,ty): rows m0 + ty + 16*i (i<8), cols tx*8 + j (j<8).
__global__ void gat_gemm(const float* __restrict__ x, const float* __restrict__ W,
                         const float* __restrict__ att_s, const float* __restrict__ att_d)
{
    extern __shared__ float sm[];
    float* xs = sm;                       // [128][XS_STRIDE]
    float* ws = sm + 128 * XS_STRIDE;     // [128][128] (k-major, same as W)

    const int tx = threadIdx.x, ty = threadIdx.y;
    const int tid = ty * 16 + tx;
    const int m0 = blockIdx.x * 128;

    // load W (128x128 = 4096 float4)
    #pragma unroll
    for (int t = 0; t < 16; t++) {
        int idx = tid + 256 * t;
        ((float4*)ws)[idx] = ((const float4*)W)[idx];
    }
    // load x tile [128][128] into padded xs, zero-pad OOB rows
    #pragma unroll
    for (int t = 0; t < 16; t++) {
        int idx = tid + 256 * t;          // 0..4095
        int r  = idx >> 5;
        int c4 = idx & 31;
        float4 v = make_float4(0.f, 0.f, 0.f, 0.f);
        int row = m0 + r;
        if (row < NN) v = ((const float4*)x)[(size_t)row * 32 + c4];
        ((float4*)(xs + (size_t)r * XS_STRIDE))[c4] = v;
    }
    __syncthreads();

    float acc[8][8];
    #pragma unroll
    for (int i = 0; i < 8; i++)
        #pragma unroll
        for (int j = 0; j < 8; j++) acc[i][j] = 0.f;

    #pragma unroll 8
    for (int k = 0; k < 128; k++) {
        float av[8];
        #pragma unroll
        for (int i = 0; i < 8; i++) av[i] = xs[(ty + 16 * i) * XS_STRIDE + k];
        float4 b0 = ((float4*)(ws + k * 128))[tx * 2];
        float4 b1 = ((float4*)(ws + k * 128))[tx * 2 + 1];
        float bv[8] = {b0.x, b0.y, b0.z, b0.w, b1.x, b1.y, b1.z, b1.w};
        #pragma unroll
        for (int i = 0; i < 8; i++)
            #pragma unroll
            for (int j = 0; j < 8; j++)
                acc[i][j] = fmaf(av[i], bv[j], acc[i][j]);
    }

    // attention vectors for this thread's 8 columns
    float4 s0 = ((const float4*)att_s)[tx * 2];
    float4 s1 = ((const float4*)att_s)[tx * 2 + 1];
    float4 d0 = ((const float4*)att_d)[tx * 2];
    float4 d1 = ((const float4*)att_d)[tx * 2 + 1];

    #pragma unroll
    for (int i = 0; i < 8; i++) {
        int row = m0 + ty + 16 * i;
        if (row < NN) {
            float4 h0 = make_float4(acc[i][0], acc[i][1], acc[i][2], acc[i][3]);
            float4 h1 = make_float4(acc[i][4], acc[i][5], acc[i][6], acc[i][7]);
            ((float4*)(g_h + (size_t)row * 128))[tx * 2]     = h0;
            ((float4*)(g_h + (size_t)row * 128))[tx * 2 + 1] = h1;
        }
        // partial dots for a_s / a_d over this thread's 8 cols
        float ps = acc[i][0]*s0.x + acc[i][1]*s0.y + acc[i][2]*s0.z + acc[i][3]*s0.w
                 + acc[i][4]*s1.x + acc[i][5]*s1.y + acc[i][6]*s1.z + acc[i][7]*s1.w;
        float pd = acc[i][0]*d0.x + acc[i][1]*d0.y + acc[i][2]*d0.z + acc[i][3]*d0.w
                 + acc[i][4]*d1.x + acc[i][5]*d1.y + acc[i][6]*d1.z + acc[i][7]*d1.w;
        // reduce across tx (lane bits 0..3; bit 4 is ty parity, untouched)
        #pragma unroll
        for (int s = 8; s; s >>= 1) {
            ps += __shfl_xor_sync(0xffffffffu, ps, s);
            pd += __shfl_xor_sync(0xffffffffu, pd, s);
        }
        if (tx == 0 && row < NN) { g_as[row] = ps; g_ad[row] = pd; }
    }
}

// ---------------- 2) CSR build ----------------
__global__ void gat_zero_deg()
{
    int i = blockIdx.x * blockDim.x + threadIdx.x;
    if (i < NN) g_deg[i] = 0;
}

__global__ void gat_hist(const int* __restrict__ dst)
{
    int i = blockIdx.x * blockDim.x + threadIdx.x;
    if (i < EE) atomicAdd(&g_deg[dst[i]], 1);
}

// single block, 1024 threads: exclusive scan of degrees -> offsets + cursors
__global__ void gat_scan()
{
    __shared__ int s[1024];
    const int tid = threadIdx.x;
    const int C = (NN + 1023) / 1024;     // 49
    int start = tid * C;
    int end = start + C; if (end > NN) end = NN;
    if (start > NN) start = NN;

    int sum = 0;
    for (int i = start; i < end; i++) sum += g_deg[i];
    s[tid] = sum;
    for (int o = 1; o < 1024; o <<= 1) {
        __syncthreads();
        int v = (tid >= o) ? s[tid - o] : 0;
        __syncthreads();
        s[tid] += v;
    }
    __syncthreads();
    int run = s[tid] - sum;               // exclusive prefix
    for (int i = start; i < end; i++) {
        g_off[i] = run;
        g_cur[i] = run;
        run += g_deg[i];
    }
    if (tid == 1023) g_off[NN] = s[1023]; // = E
}

__global__ void gat_scatter(const int* __restrict__ src, const int* __restrict__ dst)
{
    int i = blockIdx.x * blockDim.x + threadIdx.x;
    if (i >= EE) return;
    int sv = src[i], dv = dst[i];
    int pos = atomicAdd(&g_cur[dv], 1);
    float t = g_as[sv] + g_ad[dv];
    float e = t > 0.f ? t : NEG_SLOPE * t;
    g_ssrc[pos] = sv;
    g_es[pos]   = e;
}

// ---------------- 3) per-dst softmax + aggregate + fused epilogue ----------------
// one warp per destination node
__global__ void gat_aggregate(const float* __restrict__ x,
                              const float* __restrict__ bias,
                              const float* __restrict__ gamma,
                              const float* __restrict__ beta,
                              float* __restrict__ out)
{
    int u = blockIdx.x * (blockDim.x >> 5) + (threadIdx.x >> 5);
    int lane = threadIdx.x & 31;
    if (u >= NN) return;

    int o  = g_off[u];
    int oe = g_off[u + 1];
    int deg = oe - o;

    float4 acc = make_float4(0.f, 0.f, 0.f, 0.f);

    if (deg > 0) {
        // pass 1: segment max
        float m = -CUDART_INF_F;
        for (int j = lane; j < deg; j += 32) m = fmaxf(m, g_es[o + j]);
        #pragma unroll
        for (int s = 16; s; s >>= 1) m = fmaxf(m, __shfl_xor_sync(0xffffffffu, m, s));
        // pass 2: sum exp
        float sum = 0.f;
        for (int j = lane; j < deg; j += 32) sum += __expf(g_es[o + j] - m);
        #pragma unroll
        for (int s = 16; s; s >>= 1) sum += __shfl_xor_sync(0xffffffffu, sum, s);
        float inv = 1.f / sum;
        // pass 3: weighted feature gather (all lanes iterate edges together)
        for (int j = 0; j < deg; j++) {
            float alpha = __expf(g_es[o + j] - m) * inv;   // broadcast load
            int sidx = g_ssrc[o + j];                      // broadcast load
            float4 hv = ((const float4*)(g_h + (size_t)sidx * 128))[lane];
            acc.x = fmaf(alpha, hv.x, acc.x);
            acc.y = fmaf(alpha, hv.y, acc.y);
            acc.z = fmaf(alpha, hv.z, acc.z);
            acc.w = fmaf(alpha, hv.w, acc.w);
        }
    }

    // epilogue: bias -> BN(eval) -> ReLU -> residual
    const float inv_s = rsqrtf(1.0f + 1e-5f);
    float4 bv = ((const float4*)bias)[lane];
    float4 gv = ((const float4*)gamma)[lane];
    float4 be = ((const float4*)beta)[lane];
    float4 xv = ((const float4*)(x + (size_t)u * 128))[lane];

    float4 r;
    r.x = xv.x + fmaxf(gv.x * ((acc.x + bv.x) * inv_s) + be.x, 0.f);
    r.y = xv.y + fmaxf(gv.y * ((acc.y + bv.y) * inv_s) + be.y, 0.f);
    r.z = xv.z + fmaxf(gv.z * ((acc.z + bv.z) * inv_s) + be.z, 0.f);
    r.w = xv.w + fmaxf(gv.w * ((acc.w + bv.w) * inv_s) + be.w, 0.f);

    ((float4*)(out + (size_t)u * 128))[lane] = r;
}

// ---------------- stream/event handles (created pre-baseline, once) ----------------
struct StreamInit {
    cudaStream_t s;
    cudaEvent_t  eFork, eJoin;
    StreamInit() {
        cudaStreamCreateWithFlags(&s, cudaStreamNonBlocking);
        cudaEventCreateWithFlags(&eFork, cudaEventDisableTiming);
        cudaEventCreateWithFlags(&eJoin, cudaEventDisableTiming);
    }
};
static StreamInit g_si;

// ---------------- launch ----------------
extern "C" void kernel_launch(void* const* d_in, const int* in_sizes, int n_in,
                              void* d_out, int out_size)
{
    const float* x        = (const float*)d_in[0];
    const int*   edge     = (const int*)d_in[1];   // [2, E]: src row then dst row
    const float* W        = (const float*)d_in[2];
    const float* att_src  = (const float*)d_in[3];
    const float* att_dst  = (const float*)d_in[4];
    const float* bias     = (const float*)d_in[5];
    const float* gamma    = (const float*)d_in[6];
    const float* beta     = (const float*)d_in[7];
    float* out            = (float*)d_out;

    const int* src = edge;
    const int* dst = edge + EE;

    static const size_t GEMM_SMEM = (128 * XS_STRIDE + 128 * 128) * sizeof(float);
    cudaFuncSetAttribute(gat_gemm, cudaFuncAttributeMaxDynamicSharedMemorySize,
                         (int)GEMM_SMEM);

    // fork: CSR build (depends only on dst) runs concurrently with GEMM
    cudaEventRecord(g_si.eFork, 0);
    cudaStreamWaitEvent(g_si.s, g_si.eFork, 0);
    gat_zero_deg<<<(NN + 255) / 256, 256, 0, g_si.s>>>();
    gat_hist<<<(EE + 255) / 256, 256, 0, g_si.s>>>(dst);
    gat_scan<<<1, 1024, 0, g_si.s>>>();
    cudaEventRecord(g_si.eJoin, g_si.s);

    dim3 gemmBlock(16, 16);
    gat_gemm<<<(NN + 127) / 128, gemmBlock, GEMM_SMEM>>>(x, W, att_src, att_dst);

    // join: scatter needs a_s/a_d (gemm) + cursors (scan)
    cudaStreamWaitEvent(0, g_si.eJoin, 0);
    gat_scatter<<<(EE + 255) / 256, 256>>>(src, dst);

    gat_aggregate<<<(NN + 7) / 8, 256>>>(x, bias, gamma, beta, out);
}

// round 3
// speedup vs baseline: 1.1869x; 1.0236x over previous
#include <cuda_runtime.h>
#include <cuda_bf16.h>
#include <math_constants.h>

#define NN 50000
#define EE 800000
#define DD 128
#define NEG_SLOPE 0.2f
#define XS_STRIDE 132   // padded to break bank conflicts

// ---------------- device scratch (static, no allocation) ----------------
__device__ float g_h[(size_t)NN * DD];   // transformed features
__device__ float g_as[NN];
__device__ float g_ad[NN];
__device__ int   g_deg[NN];
__device__ int   g_off[NN + 1];
__device__ int   g_cur[NN];
__device__ int   g_pos[EE];              // CSR slot per edge (built in fork stream)
__device__ int   g_ssrc[EE];             // edge src sorted by dst (fork stream)
__device__ float g_es[EE];               // exp(leaky(e)) sorted by dst

// ---------------- 1) GEMM: h = x @ W, fused a_s/a_d epilogue ----------------
// 128x128x128 tile, blockDim (32,16) = 512 thr, 8x4 microtile per thread.
// Thread (tx,ty): rows m0 + ty + 16*i (i<8), cols tx*4 + j (j<4).
__global__ void gat_gemm(const float* __restrict__ x, const float* __restrict__ W,
                         const float* __restrict__ att_s, const float* __restrict__ att_d)
{
    extern __shared__ float sm[];
    float* xs = sm;                       // [128][XS_STRIDE]
    float* ws = sm + 128 * XS_STRIDE;     // [128][128] (k-major, same as W)

    const int tx = threadIdx.x, ty = threadIdx.y;
    const int tid = ty * 32 + tx;
    const int m0 = blockIdx.x * 128;

    // load W (128x128 = 4096 float4), 8 per thread
    #pragma unroll
    for (int t = 0; t < 8; t++) {
        int idx = tid + 512 * t;
        ((float4*)ws)[idx] = ((const float4*)W)[idx];
    }
    // load x tile [128][128] into padded xs, zero-pad OOB rows
    #pragma unroll
    for (int t = 0; t < 8; t++) {
        int idx = tid + 512 * t;          // 0..4095
        int r  = idx >> 5;
        int c4 = idx & 31;
        float4 v = make_float4(0.f, 0.f, 0.f, 0.f);
        int row = m0 + r;
        if (row < NN) v = ((const float4*)x)[(size_t)row * 32 + c4];
        ((float4*)(xs + (size_t)r * XS_STRIDE))[c4] = v;
    }
    __syncthreads();

    float acc[8][4];
    #pragma unroll
    for (int i = 0; i < 8; i++)
        #pragma unroll
        for (int j = 0; j < 4; j++) acc[i][j] = 0.f;

    #pragma unroll 8
    for (int k = 0; k < 128; k++) {
        float av[8];
        #pragma unroll
        for (int i = 0; i < 8; i++) av[i] = xs[(ty + 16 * i) * XS_STRIDE + k];
        float4 b = ((float4*)(ws + k * 128))[tx];
        #pragma unroll
        for (int i = 0; i < 8; i++) {
            acc[i][0] = fmaf(av[i], b.x, acc[i][0]);
            acc[i][1] = fmaf(av[i], b.y, acc[i][1]);
            acc[i][2] = fmaf(av[i], b.z, acc[i][2]);
            acc[i][3] = fmaf(av[i], b.w, acc[i][3]);
        }
    }

    // attention vectors for this thread's 4 columns
    float4 s = ((const float4*)att_s)[tx];
    float4 d = ((const float4*)att_d)[tx];

    #pragma unroll
    for (int i = 0; i < 8; i++) {
        int row = m0 + ty + 16 * i;
        float4 hv = make_float4(acc[i][0], acc[i][1], acc[i][2], acc[i][3]);
        if (row < NN)
            ((float4*)(g_h + (size_t)row * 128))[tx] = hv;
        float ps = hv.x * s.x + hv.y * s.y + hv.z * s.z + hv.w * s.w;
        float pd = hv.x * d.x + hv.y * d.y + hv.z * d.z + hv.w * d.w;
        #pragma unroll
        for (int o = 16; o; o >>= 1) {
            ps += __shfl_xor_sync(0xffffffffu, ps, o);
            pd += __shfl_xor_sync(0xffffffffu, pd, o);
        }
        if (tx == 0 && row < NN) { g_as[row] = ps; g_ad[row] = pd; }
    }
}

// ---------------- 2) CSR build (fork stream — independent of GEMM) ----------------
__global__ void gat_zero_deg()
{
    int i = blockIdx.x * blockDim.x + threadIdx.x;
    if (i < NN) g_deg[i] = 0;
}

__global__ void gat_hist(const int* __restrict__ dst)
{
    int i = blockIdx.x * blockDim.x + threadIdx.x;
    if (i < EE) atomicAdd(&g_deg[dst[i]], 1);
}

// single block, 1024 threads: exclusive scan of degrees -> offsets + cursors
__global__ void gat_scan()
{
    __shared__ int s[1024];
    const int tid = threadIdx.x;
    const int C = (NN + 1023) / 1024;     // 49
    int start = tid * C;
    int end = start + C; if (end > NN) end = NN;
    if (start > NN) start = NN;

    int sum = 0;
    for (int i = start; i < end; i++) sum += g_deg[i];
    s[tid] = sum;
    for (int o = 1; o < 1024; o <<= 1) {
        __syncthreads();
        int v = (tid >= o) ? s[tid - o] : 0;
        __syncthreads();
        s[tid] += v;
    }
    __syncthreads();
    int run = s[tid] - sum;               // exclusive prefix
    for (int i = start; i < end; i++) {
        g_off[i] = run;
        g_cur[i] = run;
        run += g_deg[i];
    }
    if (tid == 1023) g_off[NN] = s[1023]; // = E
}

// assign CSR slot + scatter src index (no dependence on GEMM outputs)
__global__ void gat_build(const int* __restrict__ src, const int* __restrict__ dst)
{
    int i = blockIdx.x * blockDim.x + threadIdx.x;
    if (i >= EE) return;
    int dv = dst[i];
    int pos = atomicAdd(&g_cur[dv], 1);
    g_pos[i]    = pos;
    g_ssrc[pos] = src[i];
}

// ---------------- 3) per-edge p = exp(leakyrelu(a_s[src]+a_d[dst])) ----------------
// softmax is shift-invariant; logits are O(1) so no max-subtraction needed.
__global__ void gat_edge(const int* __restrict__ src, const int* __restrict__ dst)
{
    int i = blockIdx.x * blockDim.x + threadIdx.x;
    if (i >= EE) return;
    float t = g_as[src[i]] + g_ad[dst[i]];
    float e = t > 0.f ? t : NEG_SLOPE * t;
    g_es[g_pos[i]] = __expf(e);
}

// ---------------- 4) per-dst normalize + aggregate + fused epilogue ----------------
// one warp per destination node; gathers batched x4 for MLP
__global__ void gat_aggregate(const float* __restrict__ x,
                              const float* __restrict__ bias,
                              const float* __restrict__ gamma,
                              const float* __restrict__ beta,
                              float* __restrict__ out)
{
    int u = blockIdx.x * (blockDim.x >> 5) + (threadIdx.x >> 5);
    int lane = threadIdx.x & 31;
    if (u >= NN) return;

    int o   = g_off[u];
    int deg = g_off[u + 1] - o;

    float4 acc = make_float4(0.f, 0.f, 0.f, 0.f);

    if (deg > 0) {
        // pass A: denom (contiguous)
        float sum = 0.f;
        for (int j = lane; j < deg; j += 32) sum += g_es[o + j];
        #pragma unroll
        for (int sh = 16; sh; sh >>= 1) sum += __shfl_xor_sync(0xffffffffu, sum, sh);
        float inv = 1.f / sum;

        // pass B: weighted gather, 4 edges in flight
        for (int j0 = 0; j0 < deg; j0 += 4) {
            float p4[4]; int s4[4];
            #pragma unroll
            for (int t = 0; t < 4; t++) {
                int j = j0 + t;
                bool v = j < deg;
                int jj = v ? j : 0;
                s4[t] = g_ssrc[o + jj];
                p4[t] = v ? g_es[o + jj] * inv : 0.f;
            }
            float4 hv4[4];
            #pragma unroll
            for (int t = 0; t < 4; t++)
                hv4[t] = ((const float4*)(g_h + (size_t)s4[t] * 128))[lane];
            #pragma unroll
            for (int t = 0; t < 4; t++) {
                acc.x = fmaf(p4[t], hv4[t].x, acc.x);
                acc.y = fmaf(p4[t], hv4[t].y, acc.y);
                acc.z = fmaf(p4[t], hv4[t].z, acc.z);
                acc.w = fmaf(p4[t], hv4[t].w, acc.w);
            }
        }
    }

    // epilogue: bias -> BN(eval) -> ReLU -> residual
    const float inv_s = rsqrtf(1.0f + 1e-5f);
    float4 bv = ((const float4*)bias)[lane];
    float4 gv = ((const float4*)gamma)[lane];
    float4 be = ((const float4*)beta)[lane];
    float4 xv = ((const float4*)(x + (size_t)u * 128))[lane];

    float4 r;
    r.x = xv.x + fmaxf(gv.x * ((acc.x + bv.x) * inv_s) + be.x, 0.f);
    r.y = xv.y + fmaxf(gv.y * ((acc.y + bv.y) * inv_s) + be.y, 0.f);
    r.z = xv.z + fmaxf(gv.z * ((acc.z + bv.z) * inv_s) + be.z, 0.f);
    r.w = xv.w + fmaxf(gv.w * ((acc.w + bv.w) * inv_s) + be.w, 0.f);

    ((float4*)(out + (size_t)u * 128))[lane] = r;
}

// ---------------- stream/event handles (created pre-baseline, once) ----------------
struct StreamInit {
    cudaStream_t s;
    cudaEvent_t  eFork, eJoin;
    StreamInit() {
        cudaStreamCreateWithFlags(&s, cudaStreamNonBlocking);
        cudaEventCreateWithFlags(&eFork, cudaEventDisableTiming);
        cudaEventCreateWithFlags(&eJoin, cudaEventDisableTiming);
    }
};
static StreamInit g_si;

// ---------------- launch ----------------
extern "C" void kernel_launch(void* const* d_in, const int* in_sizes, int n_in,
                              void* d_out, int out_size)
{
    const float* x        = (const float*)d_in[0];
    const int*   edge     = (const int*)d_in[1];   // [2, E]: src row then dst row
    const float* W        = (const float*)d_in[2];
    const float* att_src  = (const float*)d_in[3];
    const float* att_dst  = (const float*)d_in[4];
    const float* bias     = (const float*)d_in[5];
    const float* gamma    = (const float*)d_in[6];
    const float* beta     = (const float*)d_in[7];
    float* out            = (float*)d_out;

    const int* src = edge;
    const int* dst = edge + EE;

    static const size_t GEMM_SMEM = (128 * XS_STRIDE + 128 * 128) * sizeof(float);
    cudaFuncSetAttribute(gat_gemm, cudaFuncAttributeMaxDynamicSharedMemorySize,
                         (int)GEMM_SMEM);

    // fork: full CSR structure build (depends only on edge_index), hidden under GEMM
    cudaEventRecord(g_si.eFork, 0);
    cudaStreamWaitEvent(g_si.s, g_si.eFork, 0);
    gat_zero_deg<<<(NN + 255) / 256, 256, 0, g_si.s>>>();
    gat_hist<<<(EE + 255) / 256, 256, 0, g_si.s>>>(dst);
    gat_scan<<<1, 1024, 0, g_si.s>>>();
    gat_build<<<(EE + 255) / 256, 256, 0, g_si.s>>>(src, dst);
    cudaEventRecord(g_si.eJoin, g_si.s);

    dim3 gemmBlock(32, 16);
    gat_gemm<<<(NN + 127) / 128, gemmBlock, GEMM_SMEM>>>(x, W, att_src, att_dst);

    // join: edge pass needs a_s/a_d (gemm) + slots (build)
    cudaStreamWaitEvent(0, g_si.eJoin, 0);
    gat_edge<<<(EE + 255) / 256, 256>>>(src, dst);

    gat_aggregate<<<(NN + 7) / 8, 256>>>(x, bias, gamma, beta, out);
}